// round 15
// baseline (speedup 1.0000x reference)
#include <cuda_runtime.h>
#include <cuda_fp16.h>
#include <cstdint>

#define P_RAYS 2048
#define NSAMP  131072
#define SUPER  128
#define NBLK   (NSAMP / SUPER)   // 1024
#define NTHR   512
#define NCTA   148
#define PAIRS  4

// ---------------- smem layout (bytes) ----------------
#define OFF_W0   0        // weight tiles: 128 rows x 256B, XOR swizzled
#define OFF_W1   32768
#define OFF_W2   65536
#define OFF_WH   98304
#define OFF_A0   131072   // activations: 256 rows (tile pair), in-place
#define OFF_SAMP (OFF_A0 + 32768)  // float4[128] {alpha,r,g,b} (rows 128..255 of A0)
#define OFF_FS   196608   // feat_s: 128 rows
#define OFF_B0   229376   // f16[128]
#define OFF_B1   229632
#define OFF_B2   229888
#define OFF_BH   230144   // f16[128] = [ba0|br0]
#define OFF_WA1  230400   // f16[64]
#define OFF_WR1  230528   // f16[192]
#define OFF_WN   230912   // f32[256]
#define SMEM_TOTAL 231936

__device__ __forceinline__ uint32_t smem_u32(const void* p) {
    uint32_t a;
    asm("{ .reg .u64 t; cvta.to.shared.u64 t, %1; cvt.u32.u64 %0, t; }" : "=r"(a) : "l"(p));
    return a;
}
__device__ __forceinline__ uint32_t tadr(int row, int col /*half idx*/) {
    return (uint32_t)(row * 256 + ((((col >> 3) ^ (row & 7))) << 4) + ((col & 7) << 1));
}
__device__ __forceinline__ float lrelu(float x) { return fmaxf(x, 0.1f * x); }
__device__ __forceinline__ __half2 biaslrelu2(float x, float y, __half2 bb) {
    __half2 v = __hadd2(__floats2half2_rn(x, y), bb);
    return __hmax2(v, __hmul2(v, __floats2half2_rn(0.1f, 0.1f)));
}
__device__ __forceinline__ uint32_t ph2(float x, float y) {
    __half2 h = __floats2half2_rn(x, y);
    return *(uint32_t*)&h;
}
__device__ __forceinline__ uint32_t hadd2u(uint32_t a, uint32_t b) {
    __half2 r = __hadd2(*(__half2*)&a, *(__half2*)&b);
    return *(uint32_t*)&r;
}
__device__ __forceinline__ void ldsm4(uint32_t addr, uint32_t& r0, uint32_t& r1,
                                      uint32_t& r2, uint32_t& r3) {
    asm volatile("ldmatrix.sync.aligned.m8n8.x4.shared.b16 {%0,%1,%2,%3}, [%4];"
                 : "=r"(r0), "=r"(r1), "=r"(r2), "=r"(r3) : "r"(addr));
}
__device__ __forceinline__ void mma16816(float* c, uint32_t a0, uint32_t a1,
                                         uint32_t a2, uint32_t a3,
                                         uint32_t b0, uint32_t b1) {
    asm volatile(
        "mma.sync.aligned.m16n8k16.row.col.f32.f16.f16.f32 "
        "{%0,%1,%2,%3},{%4,%5,%6,%7},{%8,%9},{%0,%1,%2,%3};"
        : "+f"(c[0]), "+f"(c[1]), "+f"(c[2]), "+f"(c[3])
        : "r"(a0), "r"(a1), "r"(a2), "r"(a3), "r"(b0), "r"(b1));
}
__device__ __forceinline__ void rg_bar(int rg) {
    asm volatile("bar.sync %0, %1;" :: "r"(rg + 1), "r"(128) : "memory");
}
__device__ __forceinline__ void l2hint(const void* p) {
    asm volatile("prefetch.global.L2 [%0];" :: "l"(p));
}

// Pair GEMM: warp computes rows [R,R+32) of BOTH tiles x cols [C,C+32).
// Software-pipelined: k+1's 6 fragments (4A+2B) are loaded BEFORE k's MMA burst.
template <int KS>
__device__ __forceinline__ void layer_mma_pair(uint32_t aB, uint32_t wB, int R, int C,
                                               int lane, float acc[16][4]) {
#pragma unroll
    for (int i = 0; i < 16; i++) {
        acc[i][0] = 0.f; acc[i][1] = 0.f; acc[i][2] = 0.f; acc[i][3] = 0.f;
    }
    const int mat = lane >> 3, rl = lane & 7;
    const int half8 = (mat & 1) << 3;
    const int khi = (mat >> 1) & 1;
    const int bnt = (mat >> 1) & 1;
    const int bkh = mat & 1;
    const int ar0 = R + half8 + rl;
    const uint32_t r0a = aB + ar0 * 256;
    const uint32_t r1a = r0a + 16 * 256;
    const uint32_t r2a = r0a + 128 * 256;
    const uint32_t r3a = r2a + 16 * 256;
    const int ax = ar0 & 7;
    const int nr0 = C + bnt * 8 + rl;
    const int nr1 = C + (2 + bnt) * 8 + rl;
    const uint32_t wR0 = wB + nr0 * 256;
    const uint32_t wR1 = wB + nr1 * 256;
    const int wx0 = nr0 & 7, wx1 = nr1 & 7;

    uint32_t F[2][24];
#define LOADK(kk, buf) do {                                                   \
        const uint32_t aoff_ = (uint32_t)((((kk) * 2 + khi) ^ ax) << 4);      \
        const int kb_ = (kk) * 2 + bkh;                                       \
        ldsm4(r0a + aoff_, (buf)[0],  (buf)[1],  (buf)[2],  (buf)[3]);        \
        ldsm4(r1a + aoff_, (buf)[4],  (buf)[5],  (buf)[6],  (buf)[7]);        \
        ldsm4(r2a + aoff_, (buf)[8],  (buf)[9],  (buf)[10], (buf)[11]);       \
        ldsm4(r3a + aoff_, (buf)[12], (buf)[13], (buf)[14], (buf)[15]);       \
        ldsm4(wR0 + ((kb_ ^ wx0) << 4), (buf)[16], (buf)[17], (buf)[18], (buf)[19]); \
        ldsm4(wR1 + ((kb_ ^ wx1) << 4), (buf)[20], (buf)[21], (buf)[22], (buf)[23]); \
    } while (0)

    LOADK(0, F[0]);
#pragma unroll
    for (int k = 0; k < KS; k++) {
        uint32_t* c_ = F[k & 1];
        if (k + 1 < KS) LOADK(k + 1, F[(k + 1) & 1]);
        mma16816(acc[0],  c_[0],  c_[1],  c_[2],  c_[3],  c_[16], c_[17]);
        mma16816(acc[1],  c_[0],  c_[1],  c_[2],  c_[3],  c_[18], c_[19]);
        mma16816(acc[4],  c_[4],  c_[5],  c_[6],  c_[7],  c_[16], c_[17]);
        mma16816(acc[5],  c_[4],  c_[5],  c_[6],  c_[7],  c_[18], c_[19]);
        mma16816(acc[8],  c_[8],  c_[9],  c_[10], c_[11], c_[16], c_[17]);
        mma16816(acc[9],  c_[8],  c_[9],  c_[10], c_[11], c_[18], c_[19]);
        mma16816(acc[12], c_[12], c_[13], c_[14], c_[15], c_[16], c_[17]);
        mma16816(acc[13], c_[12], c_[13], c_[14], c_[15], c_[18], c_[19]);
        mma16816(acc[2],  c_[0],  c_[1],  c_[2],  c_[3],  c_[20], c_[21]);
        mma16816(acc[3],  c_[0],  c_[1],  c_[2],  c_[3],  c_[22], c_[23]);
        mma16816(acc[6],  c_[4],  c_[5],  c_[6],  c_[7],  c_[20], c_[21]);
        mma16816(acc[7],  c_[4],  c_[5],  c_[6],  c_[7],  c_[22], c_[23]);
        mma16816(acc[10], c_[8],  c_[9],  c_[10], c_[11], c_[20], c_[21]);
        mma16816(acc[11], c_[8],  c_[9],  c_[10], c_[11], c_[22], c_[23]);
        mma16816(acc[14], c_[12], c_[13], c_[14], c_[15], c_[20], c_[21]);
        mma16816(acc[15], c_[12], c_[13], c_[14], c_[15], c_[22], c_[23]);
    }
#undef LOADK
}

// Single-tile GEMM (heads): warp rows [R,R+32) x cols [C,C+32).
template <int KS>
__device__ __forceinline__ void layer_mma(uint32_t aB, uint32_t wB, int R, int C,
                                          int lane, float acc[8][4]) {
#pragma unroll
    for (int i = 0; i < 8; i++) {
        acc[i][0] = 0.f; acc[i][1] = 0.f; acc[i][2] = 0.f; acc[i][3] = 0.f;
    }
    const int mat = lane >> 3, rl = lane & 7;
    const int half8 = (mat & 1) << 3;
    const int khi = (mat >> 1) & 1;
    const int bnt = (mat >> 1) & 1;
    const int bkh = mat & 1;
    const int ar0 = R + half8 + rl;
    const uint32_t aRow0 = aB + ar0 * 256;
    const uint32_t aRow1 = aRow0 + 16 * 256;
    const int ax = ar0 & 7;
#pragma unroll 2
    for (int k = 0; k < KS; k++) {
        const uint32_t aoff = (uint32_t)(((k * 2 + khi) ^ ax) << 4);
        uint32_t a00, a01, a02, a03, a10, a11, a12, a13;
        ldsm4(aRow0 + aoff, a00, a01, a02, a03);
        ldsm4(aRow1 + aoff, a10, a11, a12, a13);
#pragma unroll
        for (int n2 = 0; n2 < 2; n2++) {
            const int nr = C + (n2 * 2 + bnt) * 8 + rl;
            uint32_t b0, b1, b2, b3;
            ldsm4(wB + nr * 256 + (((k * 2 + bkh) ^ (nr & 7)) << 4), b0, b1, b2, b3);
            mma16816(acc[n2 * 2 + 0], a00, a01, a02, a03, b0, b1);
            mma16816(acc[n2 * 2 + 1], a00, a01, a02, a03, b2, b3);
            mma16816(acc[4 + n2 * 2 + 0], a10, a11, a12, a13, b0, b1);
            mma16816(acc[4 + n2 * 2 + 1], a10, a11, a12, a13, b2, b3);
        }
    }
}

// Store one gathered point row into A0 with 16B vector stores.
__device__ __forceinline__ void store_rows(char* A0p, int row, float4 v0, float4 v1,
                                           float4 v2, float4 v3, int q, float oax,
                                           float* WNf) {
    const int rx = row & 7;
    const uint32_t rowB = (uint32_t)row * 256;
    uint4 f0, f1;
    f0.x = ph2(v0.x, v0.y); f0.y = ph2(v0.z, v0.w);
    f0.z = ph2(v1.x, v1.y); f0.w = ph2(v1.z, v1.w);
    f1.x = ph2(v2.x, v2.y); f1.y = ph2(v2.z, v2.w);
    f1.z = ph2(v3.x, v3.y); f1.w = ph2(v3.z, v3.w);
    *(uint4*)(A0p + rowB + (((q * 2) ^ rx) << 4)) = f0;
    *(uint4*)(A0p + rowB + (((q * 2 + 1) ^ rx) << 4)) = f1;
    float o2 = oax * oax;
    o2 += __shfl_xor_sync(0xFFFFFFFFu, o2, 1);
    o2 += __shfl_xor_sync(0xFFFFFFFFu, o2, 2);   // |offset|^2 on all 4 lanes
    if (q) {
        float sn[4], cs[4], fr = 1.f;
#pragma unroll
        for (int i = 0; i < 4; i++) { __sincosf(oax * fr, &sn[i], &cs[i]); fr *= 2.f; }
        uint4 pe;
        pe.x = ph2(sn[0], sn[1]); pe.y = ph2(sn[2], sn[3]);
        pe.z = ph2(cs[0], cs[1]); pe.w = ph2(cs[2], cs[3]);
        *(uint4*)(A0p + rowB + (((8 + q - 1) ^ rx) << 4)) = pe;
    } else {
        *(uint4*)(A0p + rowB + ((11 ^ rx) << 4)) = make_uint4(0u, 0u, 0u, 0u);
        float wraw = __expf(-10.f * sqrtf(o2));
        float ssum = wraw;
        ssum += __shfl_xor_sync(0x11111111u, ssum, 4);
        ssum += __shfl_xor_sync(0x11111111u, ssum, 8);
        ssum += __shfl_xor_sync(0x11111111u, ssum, 16);
        WNf[row] = wraw / ssum;
    }
}

__global__ __launch_bounds__(NTHR, 1) void nerf_main(
    const float* __restrict__ map_xyz, const float* __restrict__ map_feat,
    const int* __restrict__ ind_voxel, const float* __restrict__ sample_xyz,
    const float* __restrict__ dist_cam,
    const float* __restrict__ W0, const float* __restrict__ b0,
    const float* __restrict__ W1, const float* __restrict__ b1,
    const float* __restrict__ W2, const float* __restrict__ b2,
    const float* __restrict__ Wa0, const float* __restrict__ ba0,
    const float* __restrict__ Wa1, const float* __restrict__ ba1,
    const float* __restrict__ Wr0, const float* __restrict__ br0,
    const float* __restrict__ Wr1, const float* __restrict__ br1,
    float* __restrict__ out) {
    extern __shared__ char smem[];
    const uint32_t sb = smem_u32(smem);
    const int t = threadIdx.x;
    const int w = t >> 5, lane = t & 31;
    const int rg = w >> 2;
    const int R = rg * 32;
    const int C = (w & 3) * 32;

    __half* B0h = (__half*)(smem + OFF_B0);
    __half* B1h = (__half*)(smem + OFF_B1);
    __half* B2h = (__half*)(smem + OFF_B2);
    __half* BHh = (__half*)(smem + OFF_BH);
    __half* WA1h = (__half*)(smem + OFF_WA1);
    __half* WR1h = (__half*)(smem + OFF_WR1);
    float* WNf = (float*)(smem + OFF_WN);

    // ---------- weights -> f16 swizzled tiles (once per persistent CTA) ----------
    for (int i = t; i < 8192; i += NTHR)
        ((uint32_t*)(smem + OFF_W0))[i] = 0u;
    __syncthreads();
    for (int e = t; e < 88 * 128; e += NTHR) {
        int k = e >> 7, n = e & 127;
        *(__half*)(smem + OFF_W0 + tadr(n, k)) = __float2half_rn(W0[e]);
    }
    for (int e = t; e < 16384; e += NTHR) {
        int k = e >> 7, n = e & 127;
        uint32_t so = tadr(n, k);
        *(__half*)(smem + OFF_W1 + so) = __float2half_rn(W1[e]);
        *(__half*)(smem + OFF_W2 + so) = __float2half_rn(W2[e]);
    }
    for (int e = t; e < 8192; e += NTHR) {
        int k = e >> 6, n = e & 63;
        *(__half*)(smem + OFF_WH + tadr(n, k)) = __float2half_rn(Wa0[e]);
        *(__half*)(smem + OFF_WH + tadr(n + 64, k)) = __float2half_rn(Wr0[e]);
    }
    if (t < 128) {
        B0h[t] = __float2half_rn(b0[t]);
        B1h[t] = __float2half_rn(b1[t]);
        B2h[t] = __float2half_rn(b2[t]);
    }
    if (t < 64) {
        BHh[t] = __float2half_rn(ba0[t]);
        BHh[64 + t] = __float2half_rn(br0[t]);
        WA1h[t] = __float2half_rn(Wa1[t]);
    }
    if (t < 192) WR1h[t] = __float2half_rn(Wr1[t]);

    // ---------- gather prefetch: first actual pair = (rg skewed) ----------
    const int p = t >> 2, q = t & 3;          // p's row group == rg
    float4 fv[4];
    float oax = 0.f;
    int idx1 = 0;
    {
        const int ap0 = rg & 3;
        const int gs0 = blockIdx.x * SUPER + ap0 * 32 + (p >> 3);
        const int idx = ind_voxel[gs0 * 8 + (p & 7)];
        const float4* f4 = (const float4*)map_feat + (size_t)idx * 16 + q * 4;
        fv[0] = f4[0]; fv[1] = f4[1]; fv[2] = f4[2]; fv[3] = f4[3];
        if (q) oax = sample_xyz[gs0 * 3 + q - 1] - map_xyz[idx * 3 + q - 1];
        const int gs1 = gs0 + 16;
        idx1 = ind_voxel[gs1 * 8 + (p & 7)];
        l2hint((const float4*)map_feat + (size_t)idx1 * 16 + q * 4);
        if (q) l2hint(map_xyz + idx1 * 3);
    }
    __syncthreads();   // weights ready

    float acc[16][4];
    const int g = lane >> 2, tg = lane & 3;

    for (int bid = blockIdx.x; bid < NBLK; bid += gridDim.x) {
        for (int pp = 0; pp < PAIRS; pp++) {
            const int ap = (pp + rg) & 3;     // actual pair for this row group
            // ---------- store gathered pair rows -> A0 ----------
            {
                char* A0p = smem + OFF_A0;
                const int gs1 = bid * SUPER + ap * 32 + 16 + (p >> 3);
                const float4* f4b = (const float4*)map_feat + (size_t)idx1 * 16 + q * 4;
                float4 g0 = f4b[0], g1 = f4b[1], g2 = f4b[2], g3 = f4b[3];
                float oax1 = 0.f;
                if (q) oax1 = sample_xyz[gs1 * 3 + q - 1] - map_xyz[idx1 * 3 + q - 1];
                store_rows(A0p, p, fv[0], fv[1], fv[2], fv[3], q, oax, WNf);
                store_rows(A0p, 128 + p, g0, g1, g2, g3, q, oax1, WNf);
            }
            rg_bar(rg);

            // ---------- prefetch next pair (rg-skewed order) ----------
            {
                int nb = bid, anp;
                if (pp < 3) {
                    anp = (pp + 1 + rg) & 3;
                } else {
                    anp = rg & 3;
                    nb = bid + (int)gridDim.x;
                }
                if (nb < NBLK) {
                    const int gs0 = nb * SUPER + anp * 32 + (p >> 3);
                    const int idx = ind_voxel[gs0 * 8 + (p & 7)];
                    const float4* f4 = (const float4*)map_feat + (size_t)idx * 16 + q * 4;
                    fv[0] = f4[0]; fv[1] = f4[1]; fv[2] = f4[2]; fv[3] = f4[3];
                    if (q) oax = sample_xyz[gs0 * 3 + q - 1] - map_xyz[idx * 3 + q - 1];
                    const int gs1 = gs0 + 16;
                    idx1 = ind_voxel[gs1 * 8 + (p & 7)];
                    l2hint((const float4*)map_feat + (size_t)idx1 * 16 + q * 4);
                    if (q) l2hint(map_xyz + idx1 * 3);
                }
            }

            // ---------- layer 0 (K=96), in-place ----------
            layer_mma_pair<6>(sb + OFF_A0, sb + OFF_W0, R, C, lane, acc);
            rg_bar(rg);   // peer reads of A0 rows done
            {
                char* dst = smem + OFF_A0;
#pragma unroll
                for (int ti = 0; ti < 2; ti++) {
#pragma unroll
                    for (int mt = 0; mt < 2; mt++) {
                        int r0 = ti * 128 + R + mt * 16 + g;
#pragma unroll
                        for (int nt = 0; nt < 4; nt++) {
                            int col = C + nt * 8 + tg * 2;
                            __half2 bb = *(__half2*)((char*)B0h + col * 2);
                            float* a = acc[ti * 8 + mt * 4 + nt];
                            *(__half2*)(dst + tadr(r0, col)) = biaslrelu2(a[0], a[1], bb);
                            *(__half2*)(dst + tadr(r0 + 8, col)) = biaslrelu2(a[2], a[3], bb);
                        }
                    }
                }
            }
            rg_bar(rg);

            // ---------- layer 1, in-place ----------
            layer_mma_pair<8>(sb + OFF_A0, sb + OFF_W1, R, C, lane, acc);
            rg_bar(rg);
            {
                char* dst = smem + OFF_A0;
#pragma unroll
                for (int ti = 0; ti < 2; ti++) {
#pragma unroll
                    for (int mt = 0; mt < 2; mt++) {
                        int r0 = ti * 128 + R + mt * 16 + g;
#pragma unroll
                        for (int nt = 0; nt < 4; nt++) {
                            int col = C + nt * 8 + tg * 2;
                            __half2 bb = *(__half2*)((char*)B1h + col * 2);
                            float* a = acc[ti * 8 + mt * 4 + nt];
                            *(__half2*)(dst + tadr(r0, col)) = biaslrelu2(a[0], a[1], bb);
                            *(__half2*)(dst + tadr(r0 + 8, col)) = biaslrelu2(a[2], a[3], bb);
                        }
                    }
                }
            }
            rg_bar(rg);

            // ---------- layer 2 -> weighted K-reduce -> FS ----------
            layer_mma_pair<8>(sb + OFF_A0, sb + OFF_W2, R, C, lane, acc);
            {
                char* FSp = smem + OFF_FS;
#pragma unroll
                for (int ti = 0; ti < 2; ti++) {
#pragma unroll
                    for (int mt = 0; mt < 2; mt++) {
                        const int Rm = R + mt * 16;
                        const float wn0 = WNf[ti * 128 + Rm + g];
                        const float wn1 = WNf[ti * 128 + Rm + 8 + g];
                        const int sA = ap * 32 + ti * 16 + (Rm >> 3);
#pragma unroll
                        for (int nt = 0; nt < 4; nt++) {
                            int col = C + nt * 8 + tg * 2;
                            float2 bb = __half22float2(*(__half2*)((char*)B2h + col * 2));
                            float* a = acc[ti * 8 + mt * 4 + nt];
                            float v0 = lrelu(a[0] + bb.x) * wn0;
                            float v1 = lrelu(a[1] + bb.y) * wn0;
                            float v2 = lrelu(a[2] + bb.x) * wn1;
                            float v3 = lrelu(a[3] + bb.y) * wn1;
                            v0 += __shfl_xor_sync(0xFFFFFFFFu, v0, 4);
                            v1 += __shfl_xor_sync(0xFFFFFFFFu, v1, 4);
                            v2 += __shfl_xor_sync(0xFFFFFFFFu, v2, 4);
                            v3 += __shfl_xor_sync(0xFFFFFFFFu, v3, 4);
                            uint32_t h01 = ph2(v0, v1), h23 = ph2(v2, v3);
                            h01 = hadd2u(h01, __shfl_xor_sync(0xFFFFFFFFu, h01, 8));
                            h23 = hadd2u(h23, __shfl_xor_sync(0xFFFFFFFFu, h23, 8));
                            h01 = hadd2u(h01, __shfl_xor_sync(0xFFFFFFFFu, h01, 16));
                            h23 = hadd2u(h23, __shfl_xor_sync(0xFFFFFFFFu, h23, 16));
                            if (g == 0) {
                                *(uint32_t*)(FSp + tadr(sA, col)) = h01;
                                *(uint32_t*)(FSp + tadr(sA + 1, col)) = h23;
                            }
                        }
                    }
                }
            }
            rg_bar(rg);   // A0/WN rows reusable for next pair in this row group
        }

        __syncthreads();  // all groups' FS writes visible

        // ---------- heads: FS x [Wa0|Wr0] -> A0 rows 0..127 (hidden) ----------
        {
            float (*acc8)[4] = (float (*)[4])acc;
            layer_mma<8>(sb + OFF_FS, sb + OFF_WH, R, C, lane, acc8);
            char* dst = smem + OFF_A0;
#pragma unroll
            for (int mt = 0; mt < 2; mt++) {
                int r0 = R + mt * 16 + g;
#pragma unroll
                for (int nt = 0; nt < 4; nt++) {
                    int col = C + nt * 8 + tg * 2;
                    __half2 bh = *(__half2*)((char*)BHh + col * 2);
                    float* a = acc8[mt * 4 + nt];
                    *(__half2*)(dst + tadr(r0, col)) = biaslrelu2(a[0], a[1], bh);
                    *(__half2*)(dst + tadr(r0 + 8, col)) = biaslrelu2(a[2], a[3], bh);
                }
            }
        }
        __syncthreads();

        // ---------- final projections + sigmoid -> SAMP buffer ----------
        {
            char* Hp = smem + OFF_A0;
            float* SP = (float*)(smem + OFF_SAMP);
            if (t < 128) {                         // alpha for sample t
                float a = ba1[0];
#pragma unroll
                for (int m = 0; m < 32; m++) {
                    float2 v = __half22float2(*(__half2*)(Hp + tadr(t, 2 * m)));
                    float2 wv = __half22float2(((__half2*)WA1h)[m]);
                    a += v.x * wv.x + v.y * wv.y;
                }
                SP[t * 4 + 0] = 1.f / (1.f + __expf(-a));
            } else if (t < 256) {                  // rgb for sample t-128
                int s = t - 128;
                float a0 = br1[0], a1 = br1[1], a2 = br1[2];
#pragma unroll
                for (int m = 0; m < 32; m++) {
                    float2 v = __half22float2(*(__half2*)(Hp + tadr(s, 64 + 2 * m)));
                    int j = 2 * m;
                    a0 += v.x * __half2float(WR1h[j * 3 + 0]) + v.y * __half2float(WR1h[j * 3 + 3]);
                    a1 += v.x * __half2float(WR1h[j * 3 + 1]) + v.y * __half2float(WR1h[j * 3 + 4]);
                    a2 += v.x * __half2float(WR1h[j * 3 + 2]) + v.y * __half2float(WR1h[j * 3 + 5]);
                }
                SP[s * 4 + 1] = 1.f / (1.f + __expf(-a0));
                SP[s * 4 + 2] = 1.f / (1.f + __expf(-a1));
                SP[s * 4 + 3] = 1.f / (1.f + __expf(-a2));
            }
        }
        __syncthreads();

        // ---------- fused volume rendering: 2 rays per group ----------
        if (w < 2) {
            const int ray = bid * 2 + w;
            const float4* sp = (const float4*)(smem + OFF_SAMP) + w * 64;
            const float* dp = dist_cam + ray * 64;
            float cr = 0, cg = 0, cb = 0, cd = 0, ca = 0, carry = 0;
#pragma unroll
            for (int hh = 0; hh < 2; hh++) {
                float4 v = sp[hh * 32 + lane];
                float l = __logf(1.f - v.x + 1e-10f);
                float s = l;
#pragma unroll
                for (int o = 1; o < 32; o <<= 1) {
                    float n = __shfl_up_sync(0xFFFFFFFFu, s, o);
                    if (lane >= o) s += n;
                }
                float T = __expf(carry + s - l);    // exclusive prefix product
                float b = v.x * T;
                float d = 1.0f + 80.0f * dp[hh * 32 + lane] / 64.0f;
                cr += v.y * b; cg += v.z * b; cb += v.w * b; cd += d * b; ca += b;
                carry += __shfl_sync(0xFFFFFFFFu, s, 31);
            }
#pragma unroll
            for (int o = 16; o; o >>= 1) {
                cr += __shfl_down_sync(0xFFFFFFFFu, cr, o);
                cg += __shfl_down_sync(0xFFFFFFFFu, cg, o);
                cb += __shfl_down_sync(0xFFFFFFFFu, cb, o);
                cd += __shfl_down_sync(0xFFFFFFFFu, cd, o);
                ca += __shfl_down_sync(0xFFFFFFFFu, ca, o);
            }
            if (lane == 0) {
                out[ray * 5 + 0] = cr; out[ray * 5 + 1] = cg; out[ray * 5 + 2] = cb;
                out[ray * 5 + 3] = cd; out[ray * 5 + 4] = ca;
            }
        }
        __syncthreads();   // SAMP/A0 reads done before next group's gather stores
    }
}

extern "C" void kernel_launch(void* const* d_in, const int* in_sizes, int n_in,
                              void* d_out, int out_size) {
    cudaFuncSetAttribute(nerf_main, cudaFuncAttributeMaxDynamicSharedMemorySize,
                         SMEM_TOTAL);
    nerf_main<<<NCTA, NTHR, SMEM_TOTAL>>>(
        (const float*)d_in[0], (const float*)d_in[1], (const int*)d_in[2],
        (const float*)d_in[3], (const float*)d_in[4],
        (const float*)d_in[5], (const float*)d_in[6], (const float*)d_in[7],
        (const float*)d_in[8], (const float*)d_in[9], (const float*)d_in[10],
        (const float*)d_in[11], (const float*)d_in[12], (const float*)d_in[13],
        (const float*)d_in[14], (const float*)d_in[15], (const float*)d_in[16],
        (const float*)d_in[17], (const float*)d_in[18], (float*)d_out);
}

// round 16
// speedup vs baseline: 1.0289x; 1.0289x over previous
#include <cuda_runtime.h>
#include <cuda_fp16.h>
#include <cstdint>

#define P_RAYS 2048
#define NSAMP  131072
#define SUPER  128
#define NBLK   (NSAMP / SUPER)   // 1024
#define NTHR   512
#define NCTA   148
#define PAIRS  4

// ---------------- smem layout (bytes) ----------------
#define OFF_W0   0        // weight tiles: 128 rows x 256B, XOR swizzled
#define OFF_W1   32768
#define OFF_W2   65536
#define OFF_WH   98304
#define OFF_A0   131072   // activations: 256 rows (tile pair), in-place
#define OFF_SAMP (OFF_A0 + 32768)  // float4[128] {alpha,r,g,b} (rows 128..255 of A0)
#define OFF_FS   196608   // feat_s: 128 rows
#define OFF_B0   229376   // f16[128]
#define OFF_B1   229632
#define OFF_B2   229888
#define OFF_BH   230144   // f16[128] = [ba0|br0]
#define OFF_WA1  230400   // f16[64]
#define OFF_WR1  230528   // f16[192]
#define OFF_WN   230912   // f32[256]
#define SMEM_TOTAL 231936

__device__ __forceinline__ uint32_t smem_u32(const void* p) {
    uint32_t a;
    asm("{ .reg .u64 t; cvta.to.shared.u64 t, %1; cvt.u32.u64 %0, t; }" : "=r"(a) : "l"(p));
    return a;
}
__device__ __forceinline__ uint32_t tadr(int row, int col /*half idx*/) {
    return (uint32_t)(row * 256 + ((((col >> 3) ^ (row & 7))) << 4) + ((col & 7) << 1));
}
__device__ __forceinline__ float lrelu(float x) { return fmaxf(x, 0.1f * x); }
__device__ __forceinline__ __half2 biaslrelu2(float x, float y, __half2 bb) {
    __half2 v = __hadd2(__floats2half2_rn(x, y), bb);
    return __hmax2(v, __hmul2(v, __floats2half2_rn(0.1f, 0.1f)));
}
__device__ __forceinline__ uint32_t ph2(float x, float y) {
    __half2 h = __floats2half2_rn(x, y);
    return *(uint32_t*)&h;
}
__device__ __forceinline__ uint32_t hadd2u(uint32_t a, uint32_t b) {
    __half2 r = __hadd2(*(__half2*)&a, *(__half2*)&b);
    return *(uint32_t*)&r;
}
__device__ __forceinline__ void ldsm4(uint32_t addr, uint32_t& r0, uint32_t& r1,
                                      uint32_t& r2, uint32_t& r3) {
    asm volatile("ldmatrix.sync.aligned.m8n8.x4.shared.b16 {%0,%1,%2,%3}, [%4];"
                 : "=r"(r0), "=r"(r1), "=r"(r2), "=r"(r3) : "r"(addr));
}
__device__ __forceinline__ void mma16816(float* c, uint32_t a0, uint32_t a1,
                                         uint32_t a2, uint32_t a3,
                                         uint32_t b0, uint32_t b1) {
    asm volatile(
        "mma.sync.aligned.m16n8k16.row.col.f32.f16.f16.f32 "
        "{%0,%1,%2,%3},{%4,%5,%6,%7},{%8,%9},{%0,%1,%2,%3};"
        : "+f"(c[0]), "+f"(c[1]), "+f"(c[2]), "+f"(c[3])
        : "r"(a0), "r"(a1), "r"(a2), "r"(a3), "r"(b0), "r"(b1));
}
__device__ __forceinline__ void rg_bar(int rg) {
    asm volatile("bar.sync %0, %1;" :: "r"(rg + 1), "r"(128) : "memory");
}
__device__ __forceinline__ void l2hint(const void* p) {
    asm volatile("prefetch.global.L2 [%0];" :: "l"(p));
}

// Pair GEMM: warp computes rows [R,R+32) of BOTH tiles x cols [C,C+32).
// All 6 loads (4 A + 2 B) batched before the 16-MMA burst per k-step.
template <int KS>
__device__ __forceinline__ void layer_mma_pair(uint32_t aB, uint32_t wB, int R, int C,
                                               int lane, float acc[16][4]) {
#pragma unroll
    for (int i = 0; i < 16; i++) {
        acc[i][0] = 0.f; acc[i][1] = 0.f; acc[i][2] = 0.f; acc[i][3] = 0.f;
    }
    const int mat = lane >> 3, rl = lane & 7;
    const int half8 = (mat & 1) << 3;
    const int khi = (mat >> 1) & 1;
    const int bnt = (mat >> 1) & 1;
    const int bkh = mat & 1;
    const int ar0 = R + half8 + rl;
    const uint32_t r0a = aB + ar0 * 256;
    const uint32_t r1a = r0a + 16 * 256;
    const uint32_t r2a = r0a + 128 * 256;
    const uint32_t r3a = r2a + 16 * 256;
    const int ax = ar0 & 7;
    const int nr0 = C + bnt * 8 + rl;            // B row, ntile pair 0
    const int nr1 = C + (2 + bnt) * 8 + rl;      // B row, ntile pair 1
    const uint32_t wR0 = wB + nr0 * 256;
    const uint32_t wR1 = wB + nr1 * 256;
    const int wx0 = nr0 & 7, wx1 = nr1 & 7;
#pragma unroll 2
    for (int k = 0; k < KS; k++) {
        const uint32_t aoff = (uint32_t)(((k * 2 + khi) ^ ax) << 4);
        const int kb = k * 2 + bkh;
        uint32_t p00, p01, p02, p03, p10, p11, p12, p13;
        uint32_t q00, q01, q02, q03, q10, q11, q12, q13;
        uint32_t b00, b01, b02, b03, b10, b11, b12, b13;
        ldsm4(r0a + aoff, p00, p01, p02, p03);
        ldsm4(r1a + aoff, p10, p11, p12, p13);
        ldsm4(r2a + aoff, q00, q01, q02, q03);
        ldsm4(r3a + aoff, q10, q11, q12, q13);
        ldsm4(wR0 + ((kb ^ wx0) << 4), b00, b01, b02, b03);
        ldsm4(wR1 + ((kb ^ wx1) << 4), b10, b11, b12, b13);
        mma16816(acc[0],  p00, p01, p02, p03, b00, b01);
        mma16816(acc[1],  p00, p01, p02, p03, b02, b03);
        mma16816(acc[4],  p10, p11, p12, p13, b00, b01);
        mma16816(acc[5],  p10, p11, p12, p13, b02, b03);
        mma16816(acc[8],  q00, q01, q02, q03, b00, b01);
        mma16816(acc[9],  q00, q01, q02, q03, b02, b03);
        mma16816(acc[12], q10, q11, q12, q13, b00, b01);
        mma16816(acc[13], q10, q11, q12, q13, b02, b03);
        mma16816(acc[2],  p00, p01, p02, p03, b10, b11);
        mma16816(acc[3],  p00, p01, p02, p03, b12, b13);
        mma16816(acc[6],  p10, p11, p12, p13, b10, b11);
        mma16816(acc[7],  p10, p11, p12, p13, b12, b13);
        mma16816(acc[10], q00, q01, q02, q03, b10, b11);
        mma16816(acc[11], q00, q01, q02, q03, b12, b13);
        mma16816(acc[14], q10, q11, q12, q13, b10, b11);
        mma16816(acc[15], q10, q11, q12, q13, b12, b13);
    }
}

// Single-tile GEMM (heads): warp rows [R,R+32) x cols [C,C+32).
template <int KS>
__device__ __forceinline__ void layer_mma(uint32_t aB, uint32_t wB, int R, int C,
                                          int lane, float acc[8][4]) {
#pragma unroll
    for (int i = 0; i < 8; i++) {
        acc[i][0] = 0.f; acc[i][1] = 0.f; acc[i][2] = 0.f; acc[i][3] = 0.f;
    }
    const int mat = lane >> 3, rl = lane & 7;
    const int half8 = (mat & 1) << 3;
    const int khi = (mat >> 1) & 1;
    const int bnt = (mat >> 1) & 1;
    const int bkh = mat & 1;
    const int ar0 = R + half8 + rl;
    const uint32_t aRow0 = aB + ar0 * 256;
    const uint32_t aRow1 = aRow0 + 16 * 256;
    const int ax = ar0 & 7;
#pragma unroll 2
    for (int k = 0; k < KS; k++) {
        const uint32_t aoff = (uint32_t)(((k * 2 + khi) ^ ax) << 4);
        uint32_t a00, a01, a02, a03, a10, a11, a12, a13;
        ldsm4(aRow0 + aoff, a00, a01, a02, a03);
        ldsm4(aRow1 + aoff, a10, a11, a12, a13);
#pragma unroll
        for (int n2 = 0; n2 < 2; n2++) {
            const int nr = C + (n2 * 2 + bnt) * 8 + rl;
            uint32_t b0, b1, b2, b3;
            ldsm4(wB + nr * 256 + (((k * 2 + bkh) ^ (nr & 7)) << 4), b0, b1, b2, b3);
            mma16816(acc[n2 * 2 + 0], a00, a01, a02, a03, b0, b1);
            mma16816(acc[n2 * 2 + 1], a00, a01, a02, a03, b2, b3);
            mma16816(acc[4 + n2 * 2 + 0], a10, a11, a12, a13, b0, b1);
            mma16816(acc[4 + n2 * 2 + 1], a10, a11, a12, a13, b2, b3);
        }
    }
}

// Store one gathered point row into A0 with 16B vector stores.
__device__ __forceinline__ void store_rows(char* A0p, int row, float4 v0, float4 v1,
                                           float4 v2, float4 v3, int q, float oax,
                                           float* WNf) {
    const int rx = row & 7;
    const uint32_t rowB = (uint32_t)row * 256;
    uint4 f0, f1;
    f0.x = ph2(v0.x, v0.y); f0.y = ph2(v0.z, v0.w);
    f0.z = ph2(v1.x, v1.y); f0.w = ph2(v1.z, v1.w);
    f1.x = ph2(v2.x, v2.y); f1.y = ph2(v2.z, v2.w);
    f1.z = ph2(v3.x, v3.y); f1.w = ph2(v3.z, v3.w);
    *(uint4*)(A0p + rowB + (((q * 2) ^ rx) << 4)) = f0;
    *(uint4*)(A0p + rowB + (((q * 2 + 1) ^ rx) << 4)) = f1;
    float o2 = oax * oax;
    o2 += __shfl_xor_sync(0xFFFFFFFFu, o2, 1);
    o2 += __shfl_xor_sync(0xFFFFFFFFu, o2, 2);   // |offset|^2 on all 4 lanes
    if (q) {
        float sn[4], cs[4], fr = 1.f;
#pragma unroll
        for (int i = 0; i < 4; i++) { __sincosf(oax * fr, &sn[i], &cs[i]); fr *= 2.f; }
        uint4 pe;
        pe.x = ph2(sn[0], sn[1]); pe.y = ph2(sn[2], sn[3]);
        pe.z = ph2(cs[0], cs[1]); pe.w = ph2(cs[2], cs[3]);
        *(uint4*)(A0p + rowB + (((8 + q - 1) ^ rx) << 4)) = pe;
    } else {
        *(uint4*)(A0p + rowB + ((11 ^ rx) << 4)) = make_uint4(0u, 0u, 0u, 0u);
        float wraw = __expf(-10.f * sqrtf(o2));
        float ssum = wraw;
        ssum += __shfl_xor_sync(0x11111111u, ssum, 4);
        ssum += __shfl_xor_sync(0x11111111u, ssum, 8);
        ssum += __shfl_xor_sync(0x11111111u, ssum, 16);
        WNf[row] = wraw / ssum;
    }
}

__global__ __launch_bounds__(NTHR, 1) void nerf_main(
    const float* __restrict__ map_xyz, const float* __restrict__ map_feat,
    const int* __restrict__ ind_voxel, const float* __restrict__ sample_xyz,
    const float* __restrict__ dist_cam,
    const float* __restrict__ W0, const float* __restrict__ b0,
    const float* __restrict__ W1, const float* __restrict__ b1,
    const float* __restrict__ W2, const float* __restrict__ b2,
    const float* __restrict__ Wa0, const float* __restrict__ ba0,
    const float* __restrict__ Wa1, const float* __restrict__ ba1,
    const float* __restrict__ Wr0, const float* __restrict__ br0,
    const float* __restrict__ Wr1, const float* __restrict__ br1,
    float* __restrict__ out) {
    extern __shared__ char smem[];
    const uint32_t sb = smem_u32(smem);
    const int t = threadIdx.x;
    const int w = t >> 5, lane = t & 31;
    const int rg = w >> 2;
    const int R = rg * 32;
    const int C = (w & 3) * 32;

    __half* B0h = (__half*)(smem + OFF_B0);
    __half* B1h = (__half*)(smem + OFF_B1);
    __half* B2h = (__half*)(smem + OFF_B2);
    __half* BHh = (__half*)(smem + OFF_BH);
    __half* WA1h = (__half*)(smem + OFF_WA1);
    __half* WR1h = (__half*)(smem + OFF_WR1);
    float* WNf = (float*)(smem + OFF_WN);

    // ---------- weights -> f16 swizzled tiles (once per persistent CTA) ----------
    for (int i = t; i < 8192; i += NTHR)
        ((uint32_t*)(smem + OFF_W0))[i] = 0u;
    __syncthreads();
    for (int e = t; e < 88 * 128; e += NTHR) {
        int k = e >> 7, n = e & 127;
        *(__half*)(smem + OFF_W0 + tadr(n, k)) = __float2half_rn(W0[e]);
    }
    for (int e = t; e < 16384; e += NTHR) {
        int k = e >> 7, n = e & 127;
        uint32_t so = tadr(n, k);
        *(__half*)(smem + OFF_W1 + so) = __float2half_rn(W1[e]);
        *(__half*)(smem + OFF_W2 + so) = __float2half_rn(W2[e]);
    }
    for (int e = t; e < 8192; e += NTHR) {
        int k = e >> 6, n = e & 63;
        *(__half*)(smem + OFF_WH + tadr(n, k)) = __float2half_rn(Wa0[e]);
        *(__half*)(smem + OFF_WH + tadr(n + 64, k)) = __float2half_rn(Wr0[e]);
    }
    if (t < 128) {
        B0h[t] = __float2half_rn(b0[t]);
        B1h[t] = __float2half_rn(b1[t]);
        B2h[t] = __float2half_rn(b2[t]);
    }
    if (t < 64) {
        BHh[t] = __float2half_rn(ba0[t]);
        BHh[64 + t] = __float2half_rn(br0[t]);
        WA1h[t] = __float2half_rn(Wa1[t]);
    }
    if (t < 192) WR1h[t] = __float2half_rn(Wr1[t]);

    // ---------- gather prefetch: first actual pair = (rg skewed) ----------
    const int p = t >> 2, q = t & 3;          // p's row group == rg
    float4 fv[4];
    float oax = 0.f;
    int idx1 = 0;
    {
        const int ap0 = rg & 3;
        const int gs0 = blockIdx.x * SUPER + ap0 * 32 + (p >> 3);
        const int idx = ind_voxel[gs0 * 8 + (p & 7)];
        const float4* f4 = (const float4*)map_feat + (size_t)idx * 16 + q * 4;
        fv[0] = f4[0]; fv[1] = f4[1]; fv[2] = f4[2]; fv[3] = f4[3];
        if (q) oax = sample_xyz[gs0 * 3 + q - 1] - map_xyz[idx * 3 + q - 1];
        const int gs1 = gs0 + 16;
        idx1 = ind_voxel[gs1 * 8 + (p & 7)];
        l2hint((const float4*)map_feat + (size_t)idx1 * 16 + q * 4);
        if (q) l2hint(map_xyz + idx1 * 3);
    }
    __syncthreads();   // weights ready

    float acc[16][4];
    __half2 hv[32];
    const int g = lane >> 2, tg = lane & 3;

    for (int bid = blockIdx.x; bid < NBLK; bid += gridDim.x) {
        for (int pp = 0; pp < PAIRS; pp++) {
            const int ap = (pp + rg) & 3;     // actual pair for this row group
            // ---------- store gathered pair rows -> A0 ----------
            {
                char* A0p = smem + OFF_A0;
                const int gs1 = bid * SUPER + ap * 32 + 16 + (p >> 3);
                const float4* f4b = (const float4*)map_feat + (size_t)idx1 * 16 + q * 4;
                float4 g0 = f4b[0], g1 = f4b[1], g2 = f4b[2], g3 = f4b[3];
                float oax1 = 0.f;
                if (q) oax1 = sample_xyz[gs1 * 3 + q - 1] - map_xyz[idx1 * 3 + q - 1];
                store_rows(A0p, p, fv[0], fv[1], fv[2], fv[3], q, oax, WNf);
                store_rows(A0p, 128 + p, g0, g1, g2, g3, q, oax1, WNf);
            }
            rg_bar(rg);

            // ---------- prefetch next pair (rg-skewed order) ----------
            {
                int nb = bid, anp;
                if (pp < 3) {
                    anp = (pp + 1 + rg) & 3;
                } else {
                    anp = rg & 3;
                    nb = bid + (int)gridDim.x;
                }
                if (nb < NBLK) {
                    const int gs0 = nb * SUPER + anp * 32 + (p >> 3);
                    const int idx = ind_voxel[gs0 * 8 + (p & 7)];
                    const float4* f4 = (const float4*)map_feat + (size_t)idx * 16 + q * 4;
                    fv[0] = f4[0]; fv[1] = f4[1]; fv[2] = f4[2]; fv[3] = f4[3];
                    if (q) oax = sample_xyz[gs0 * 3 + q - 1] - map_xyz[idx * 3 + q - 1];
                    const int gs1 = gs0 + 16;
                    idx1 = ind_voxel[gs1 * 8 + (p & 7)];
                    l2hint((const float4*)map_feat + (size_t)idx1 * 16 + q * 4);
                    if (q) l2hint(map_xyz + idx1 * 3);
                }
            }

            // ---------- layer 0 (K=96), in-place ----------
            layer_mma_pair<6>(sb + OFF_A0, sb + OFF_W0, R, C, lane, acc);
            {   // compute packed epilogue BEFORE the WAR barrier (regs only)
#pragma unroll
                for (int i = 0; i < 16; i++) {
                    int nt = i & 3;
                    __half2 bb = *(__half2*)((char*)B0h + (C + nt * 8 + tg * 2) * 2);
                    hv[i * 2 + 0] = biaslrelu2(acc[i][0], acc[i][1], bb);
                    hv[i * 2 + 1] = biaslrelu2(acc[i][2], acc[i][3], bb);
                }
            }
            rg_bar(rg);   // peer reads of A0 rows done
            {
                char* dst = smem + OFF_A0;
#pragma unroll
                for (int i = 0; i < 16; i++) {
                    int ti = i >> 3, mt = (i >> 2) & 1, nt = i & 3;
                    int r0 = ti * 128 + R + mt * 16 + g;
                    int col = C + nt * 8 + tg * 2;
                    *(__half2*)(dst + tadr(r0, col)) = hv[i * 2 + 0];
                    *(__half2*)(dst + tadr(r0 + 8, col)) = hv[i * 2 + 1];
                }
            }
            rg_bar(rg);

            // ---------- layer 1, in-place ----------
            layer_mma_pair<8>(sb + OFF_A0, sb + OFF_W1, R, C, lane, acc);
            {
#pragma unroll
                for (int i = 0; i < 16; i++) {
                    int nt = i & 3;
                    __half2 bb = *(__half2*)((char*)B1h + (C + nt * 8 + tg * 2) * 2);
                    hv[i * 2 + 0] = biaslrelu2(acc[i][0], acc[i][1], bb);
                    hv[i * 2 + 1] = biaslrelu2(acc[i][2], acc[i][3], bb);
                }
            }
            rg_bar(rg);
            {
                char* dst = smem + OFF_A0;
#pragma unroll
                for (int i = 0; i < 16; i++) {
                    int ti = i >> 3, mt = (i >> 2) & 1, nt = i & 3;
                    int r0 = ti * 128 + R + mt * 16 + g;
                    int col = C + nt * 8 + tg * 2;
                    *(__half2*)(dst + tadr(r0, col)) = hv[i * 2 + 0];
                    *(__half2*)(dst + tadr(r0 + 8, col)) = hv[i * 2 + 1];
                }
            }
            rg_bar(rg);

            // ---------- layer 2 -> weighted K-reduce (all-packed) -> FS ----------
            layer_mma_pair<8>(sb + OFF_A0, sb + OFF_W2, R, C, lane, acc);
            {
                char* FSp = smem + OFF_FS;
#pragma unroll
                for (int ti = 0; ti < 2; ti++) {
#pragma unroll
                    for (int mt = 0; mt < 2; mt++) {
                        const int Rm = R + mt * 16;
                        const float wn0 = WNf[ti * 128 + Rm + g];
                        const float wn1 = WNf[ti * 128 + Rm + 8 + g];
                        const int sA = ap * 32 + ti * 16 + (Rm >> 3);
#pragma unroll
                        for (int nt = 0; nt < 4; nt++) {
                            int col = C + nt * 8 + tg * 2;
                            float2 bb = __half22float2(*(__half2*)((char*)B2h + col * 2));
                            float* a = acc[ti * 8 + mt * 4 + nt];
                            uint32_t h01 = ph2(lrelu(a[0] + bb.x) * wn0,
                                               lrelu(a[1] + bb.y) * wn0);
                            uint32_t h23 = ph2(lrelu(a[2] + bb.x) * wn1,
                                               lrelu(a[3] + bb.y) * wn1);
                            h01 = hadd2u(h01, __shfl_xor_sync(0xFFFFFFFFu, h01, 4));
                            h23 = hadd2u(h23, __shfl_xor_sync(0xFFFFFFFFu, h23, 4));
                            h01 = hadd2u(h01, __shfl_xor_sync(0xFFFFFFFFu, h01, 8));
                            h23 = hadd2u(h23, __shfl_xor_sync(0xFFFFFFFFu, h23, 8));
                            h01 = hadd2u(h01, __shfl_xor_sync(0xFFFFFFFFu, h01, 16));
                            h23 = hadd2u(h23, __shfl_xor_sync(0xFFFFFFFFu, h23, 16));
                            if (g == 0) {
                                *(uint32_t*)(FSp + tadr(sA, col)) = h01;
                                *(uint32_t*)(FSp + tadr(sA + 1, col)) = h23;
                            }
                        }
                    }
                }
            }
            rg_bar(rg);   // A0/WN rows reusable for next pair in this row group
        }

        __syncthreads();  // all groups' FS writes visible

        // ---------- heads: FS x [Wa0|Wr0] -> A0 rows 0..127 (hidden) ----------
        {
            float (*acc8)[4] = (float (*)[4])acc;
            layer_mma<8>(sb + OFF_FS, sb + OFF_WH, R, C, lane, acc8);
            char* dst = smem + OFF_A0;
#pragma unroll
            for (int mt = 0; mt < 2; mt++) {
                int r0 = R + mt * 16 + g;
#pragma unroll
                for (int nt = 0; nt < 4; nt++) {
                    int col = C + nt * 8 + tg * 2;
                    __half2 bh = *(__half2*)((char*)BHh + col * 2);
                    float* a = acc8[mt * 4 + nt];
                    *(__half2*)(dst + tadr(r0, col)) = biaslrelu2(a[0], a[1], bh);
                    *(__half2*)(dst + tadr(r0 + 8, col)) = biaslrelu2(a[2], a[3], bh);
                }
            }
        }
        __syncthreads();

        // ---------- final projections + sigmoid -> SAMP buffer ----------
        {
            char* Hp = smem + OFF_A0;
            float* SP = (float*)(smem + OFF_SAMP);
            if (t < 128) {                         // alpha for sample t
                float a = ba1[0];
#pragma unroll
                for (int m = 0; m < 32; m++) {
                    float2 v = __half22float2(*(__half2*)(Hp + tadr(t, 2 * m)));
                    float2 wv = __half22float2(((__half2*)WA1h)[m]);
                    a += v.x * wv.x + v.y * wv.y;
                }
                SP[t * 4 + 0] = 1.f / (1.f + __expf(-a));
            } else if (t < 256) {                  // rgb for sample t-128
                int s = t - 128;
                float a0 = br1[0], a1 = br1[1], a2 = br1[2];
#pragma unroll
                for (int m = 0; m < 32; m++) {
                    float2 v = __half22float2(*(__half2*)(Hp + tadr(s, 64 + 2 * m)));
                    int j = 2 * m;
                    a0 += v.x * __half2float(WR1h[j * 3 + 0]) + v.y * __half2float(WR1h[j * 3 + 3]);
                    a1 += v.x * __half2float(WR1h[j * 3 + 1]) + v.y * __half2float(WR1h[j * 3 + 4]);
                    a2 += v.x * __half2float(WR1h[j * 3 + 2]) + v.y * __half2float(WR1h[j * 3 + 5]);
                }
                SP[s * 4 + 1] = 1.f / (1.f + __expf(-a0));
                SP[s * 4 + 2] = 1.f / (1.f + __expf(-a1));
                SP[s * 4 + 3] = 1.f / (1.f + __expf(-a2));
            }
        }
        __syncthreads();

        // ---------- fused volume rendering: 2 rays per group ----------
        if (w < 2) {
            const int ray = bid * 2 + w;
            const float4* sp = (const float4*)(smem + OFF_SAMP) + w * 64;
            const float* dp = dist_cam + ray * 64;
            float cr = 0, cg = 0, cb = 0, cd = 0, ca = 0, carry = 0;
#pragma unroll
            for (int hh = 0; hh < 2; hh++) {
                float4 v = sp[hh * 32 + lane];
                float l = __logf(1.f - v.x + 1e-10f);
                float s = l;
#pragma unroll
                for (int o = 1; o < 32; o <<= 1) {
                    float n = __shfl_up_sync(0xFFFFFFFFu, s, o);
                    if (lane >= o) s += n;
                }
                float T = __expf(carry + s - l);    // exclusive prefix product
                float b = v.x * T;
                float d = 1.0f + 80.0f * dp[hh * 32 + lane] / 64.0f;
                cr += v.y * b; cg += v.z * b; cb += v.w * b; cd += d * b; ca += b;
                carry += __shfl_sync(0xFFFFFFFFu, s, 31);
            }
#pragma unroll
            for (int o = 16; o; o >>= 1) {
                cr += __shfl_down_sync(0xFFFFFFFFu, cr, o);
                cg += __shfl_down_sync(0xFFFFFFFFu, cg, o);
                cb += __shfl_down_sync(0xFFFFFFFFu, cb, o);
                cd += __shfl_down_sync(0xFFFFFFFFu, cd, o);
                ca += __shfl_down_sync(0xFFFFFFFFu, ca, o);
            }
            if (lane == 0) {
                out[ray * 5 + 0] = cr; out[ray * 5 + 1] = cg; out[ray * 5 + 2] = cb;
                out[ray * 5 + 3] = cd; out[ray * 5 + 4] = ca;
            }
        }
        __syncthreads();   // SAMP/A0 reads done before next group's gather stores
    }
}

extern "C" void kernel_launch(void* const* d_in, const int* in_sizes, int n_in,
                              void* d_out, int out_size) {
    cudaFuncSetAttribute(nerf_main, cudaFuncAttributeMaxDynamicSharedMemorySize,
                         SMEM_TOTAL);
    nerf_main<<<NCTA, NTHR, SMEM_TOTAL>>>(
        (const float*)d_in[0], (const float*)d_in[1], (const int*)d_in[2],
        (const float*)d_in[3], (const float*)d_in[4],
        (const float*)d_in[5], (const float*)d_in[6], (const float*)d_in[7],
        (const float*)d_in[8], (const float*)d_in[9], (const float*)d_in[10],
        (const float*)d_in[11], (const float*)d_in[12], (const float*)d_in[13],
        (const float*)d_in[14], (const float*)d_in[15], (const float*)d_in[16],
        (const float*)d_in[17], (const float*)d_in[18], (float*)d_out);
}

// round 17
// speedup vs baseline: 1.0558x; 1.0262x over previous
#include <cuda_runtime.h>
#include <cuda_fp16.h>
#include <cstdint>

#define P_RAYS 2048
#define NSAMP  131072
#define SUPER  128
#define NBLK   (NSAMP / SUPER)   // 1024
#define NTHR   512
#define NCTA   148
#define PAIRS  4

// ---------------- smem layout (bytes) ----------------
#define OFF_W0   0        // weight tiles: 128 rows x 256B, XOR swizzled
#define OFF_W1   32768
#define OFF_W2   65536
#define OFF_WH   98304
#define OFF_A0   131072   // activations: 256 rows (tile pair), in-place
#define OFF_SAMP (OFF_A0 + 32768)  // float4[128] {alpha,r,g,b} (rows 128..255 of A0)
#define OFF_FS   196608   // feat_s: 128 rows
#define OFF_B0   229376   // f16[128]
#define OFF_B1   229632
#define OFF_B2   229888
#define OFF_BH   230144   // f16[128] = [ba0|br0]
#define OFF_WA1  230400   // f16[64]
#define OFF_WR1  230528   // f16[192]
#define OFF_WN   230912   // f32[256]
#define SMEM_TOTAL 231936

__device__ __forceinline__ uint32_t smem_u32(const void* p) {
    uint32_t a;
    asm("{ .reg .u64 t; cvta.to.shared.u64 t, %1; cvt.u32.u64 %0, t; }" : "=r"(a) : "l"(p));
    return a;
}
__device__ __forceinline__ uint32_t tadr(int row, int col /*half idx*/) {
    return (uint32_t)(row * 256 + ((((col >> 3) ^ (row & 7))) << 4) + ((col & 7) << 1));
}
__device__ __forceinline__ float lrelu(float x) { return fmaxf(x, 0.1f * x); }
__device__ __forceinline__ __half2 biaslrelu2(float x, float y, __half2 bb) {
    __half2 v = __hadd2(__floats2half2_rn(x, y), bb);
    return __hmax2(v, __hmul2(v, __floats2half2_rn(0.1f, 0.1f)));
}
__device__ __forceinline__ uint32_t ph2(float x, float y) {
    __half2 h = __floats2half2_rn(x, y);
    return *(uint32_t*)&h;
}
__device__ __forceinline__ uint32_t hadd2u(uint32_t a, uint32_t b) {
    __half2 r = __hadd2(*(__half2*)&a, *(__half2*)&b);
    return *(uint32_t*)&r;
}
__device__ __forceinline__ void ldsm4(uint32_t addr, uint32_t& r0, uint32_t& r1,
                                      uint32_t& r2, uint32_t& r3) {
    asm volatile("ldmatrix.sync.aligned.m8n8.x4.shared.b16 {%0,%1,%2,%3}, [%4];"
                 : "=r"(r0), "=r"(r1), "=r"(r2), "=r"(r3) : "r"(addr));
}
__device__ __forceinline__ void mma16816(float* c, uint32_t a0, uint32_t a1,
                                         uint32_t a2, uint32_t a3,
                                         uint32_t b0, uint32_t b1) {
    asm volatile(
        "mma.sync.aligned.m16n8k16.row.col.f32.f16.f16.f32 "
        "{%0,%1,%2,%3},{%4,%5,%6,%7},{%8,%9},{%0,%1,%2,%3};"
        : "+f"(c[0]), "+f"(c[1]), "+f"(c[2]), "+f"(c[3])
        : "r"(a0), "r"(a1), "r"(a2), "r"(a3), "r"(b0), "r"(b1));
}
__device__ __forceinline__ void rg_bar(int rg) {
    asm volatile("bar.sync %0, %1;" :: "r"(rg + 1), "r"(128) : "memory");
}
__device__ __forceinline__ void l2hint(const void* p) {
    asm volatile("prefetch.global.L2 [%0];" :: "l"(p));
}

// Pair GEMM: warp computes rows [R,R+32) of BOTH tiles x cols [C,C+32).
// All 6 loads (4 A + 2 B) batched before the 16-MMA burst per k-step.
template <int KS>
__device__ __forceinline__ void layer_mma_pair(uint32_t aB, uint32_t wB, int R, int C,
                                               int lane, float acc[16][4]) {
#pragma unroll
    for (int i = 0; i < 16; i++) {
        acc[i][0] = 0.f; acc[i][1] = 0.f; acc[i][2] = 0.f; acc[i][3] = 0.f;
    }
    const int mat = lane >> 3, rl = lane & 7;
    const int half8 = (mat & 1) << 3;
    const int khi = (mat >> 1) & 1;
    const int bnt = (mat >> 1) & 1;
    const int bkh = mat & 1;
    const int ar0 = R + half8 + rl;
    const uint32_t r0a = aB + ar0 * 256;
    const uint32_t r1a = r0a + 16 * 256;
    const uint32_t r2a = r0a + 128 * 256;
    const uint32_t r3a = r2a + 16 * 256;
    const int ax = ar0 & 7;
    const int nr0 = C + bnt * 8 + rl;            // B row, ntile pair 0
    const int nr1 = C + (2 + bnt) * 8 + rl;      // B row, ntile pair 1
    const uint32_t wR0 = wB + nr0 * 256;
    const uint32_t wR1 = wB + nr1 * 256;
    const int wx0 = nr0 & 7, wx1 = nr1 & 7;
#pragma unroll 2
    for (int k = 0; k < KS; k++) {
        const uint32_t aoff = (uint32_t)(((k * 2 + khi) ^ ax) << 4);
        const int kb = k * 2 + bkh;
        uint32_t p00, p01, p02, p03, p10, p11, p12, p13;
        uint32_t q00, q01, q02, q03, q10, q11, q12, q13;
        uint32_t b00, b01, b02, b03, b10, b11, b12, b13;
        ldsm4(r0a + aoff, p00, p01, p02, p03);
        ldsm4(r1a + aoff, p10, p11, p12, p13);
        ldsm4(r2a + aoff, q00, q01, q02, q03);
        ldsm4(r3a + aoff, q10, q11, q12, q13);
        ldsm4(wR0 + ((kb ^ wx0) << 4), b00, b01, b02, b03);
        ldsm4(wR1 + ((kb ^ wx1) << 4), b10, b11, b12, b13);
        mma16816(acc[0],  p00, p01, p02, p03, b00, b01);
        mma16816(acc[1],  p00, p01, p02, p03, b02, b03);
        mma16816(acc[4],  p10, p11, p12, p13, b00, b01);
        mma16816(acc[5],  p10, p11, p12, p13, b02, b03);
        mma16816(acc[8],  q00, q01, q02, q03, b00, b01);
        mma16816(acc[9],  q00, q01, q02, q03, b02, b03);
        mma16816(acc[12], q10, q11, q12, q13, b00, b01);
        mma16816(acc[13], q10, q11, q12, q13, b02, b03);
        mma16816(acc[2],  p00, p01, p02, p03, b10, b11);
        mma16816(acc[3],  p00, p01, p02, p03, b12, b13);
        mma16816(acc[6],  p10, p11, p12, p13, b10, b11);
        mma16816(acc[7],  p10, p11, p12, p13, b12, b13);
        mma16816(acc[10], q00, q01, q02, q03, b10, b11);
        mma16816(acc[11], q00, q01, q02, q03, b12, b13);
        mma16816(acc[14], q10, q11, q12, q13, b10, b11);
        mma16816(acc[15], q10, q11, q12, q13, b12, b13);
    }
}

// Single-tile GEMM (heads): warp rows [R,R+32) x cols [C,C+32).
template <int KS>
__device__ __forceinline__ void layer_mma(uint32_t aB, uint32_t wB, int R, int C,
                                          int lane, float acc[8][4]) {
#pragma unroll
    for (int i = 0; i < 8; i++) {
        acc[i][0] = 0.f; acc[i][1] = 0.f; acc[i][2] = 0.f; acc[i][3] = 0.f;
    }
    const int mat = lane >> 3, rl = lane & 7;
    const int half8 = (mat & 1) << 3;
    const int khi = (mat >> 1) & 1;
    const int bnt = (mat >> 1) & 1;
    const int bkh = mat & 1;
    const int ar0 = R + half8 + rl;
    const uint32_t aRow0 = aB + ar0 * 256;
    const uint32_t aRow1 = aRow0 + 16 * 256;
    const int ax = ar0 & 7;
#pragma unroll 2
    for (int k = 0; k < KS; k++) {
        const uint32_t aoff = (uint32_t)(((k * 2 + khi) ^ ax) << 4);
        uint32_t a00, a01, a02, a03, a10, a11, a12, a13;
        ldsm4(aRow0 + aoff, a00, a01, a02, a03);
        ldsm4(aRow1 + aoff, a10, a11, a12, a13);
#pragma unroll
        for (int n2 = 0; n2 < 2; n2++) {
            const int nr = C + (n2 * 2 + bnt) * 8 + rl;
            uint32_t b0, b1, b2, b3;
            ldsm4(wB + nr * 256 + (((k * 2 + bkh) ^ (nr & 7)) << 4), b0, b1, b2, b3);
            mma16816(acc[n2 * 2 + 0], a00, a01, a02, a03, b0, b1);
            mma16816(acc[n2 * 2 + 1], a00, a01, a02, a03, b2, b3);
            mma16816(acc[4 + n2 * 2 + 0], a10, a11, a12, a13, b0, b1);
            mma16816(acc[4 + n2 * 2 + 1], a10, a11, a12, a13, b2, b3);
        }
    }
}

// Store one gathered point row into A0 with 16B vector stores.
__device__ __forceinline__ void store_rows(char* A0p, int row, float4 v0, float4 v1,
                                           float4 v2, float4 v3, int q, float oax,
                                           float* WNf) {
    const int rx = row & 7;
    const uint32_t rowB = (uint32_t)row * 256;
    uint4 f0, f1;
    f0.x = ph2(v0.x, v0.y); f0.y = ph2(v0.z, v0.w);
    f0.z = ph2(v1.x, v1.y); f0.w = ph2(v1.z, v1.w);
    f1.x = ph2(v2.x, v2.y); f1.y = ph2(v2.z, v2.w);
    f1.z = ph2(v3.x, v3.y); f1.w = ph2(v3.z, v3.w);
    *(uint4*)(A0p + rowB + (((q * 2) ^ rx) << 4)) = f0;
    *(uint4*)(A0p + rowB + (((q * 2 + 1) ^ rx) << 4)) = f1;
    float o2 = oax * oax;
    o2 += __shfl_xor_sync(0xFFFFFFFFu, o2, 1);
    o2 += __shfl_xor_sync(0xFFFFFFFFu, o2, 2);   // |offset|^2 on all 4 lanes
    if (q) {
        float sn[4], cs[4], fr = 1.f;
#pragma unroll
        for (int i = 0; i < 4; i++) { __sincosf(oax * fr, &sn[i], &cs[i]); fr *= 2.f; }
        uint4 pe;
        pe.x = ph2(sn[0], sn[1]); pe.y = ph2(sn[2], sn[3]);
        pe.z = ph2(cs[0], cs[1]); pe.w = ph2(cs[2], cs[3]);
        *(uint4*)(A0p + rowB + (((8 + q - 1) ^ rx) << 4)) = pe;
    } else {
        *(uint4*)(A0p + rowB + ((11 ^ rx) << 4)) = make_uint4(0u, 0u, 0u, 0u);
        float wraw = __expf(-10.f * sqrtf(o2));
        float ssum = wraw;
        ssum += __shfl_xor_sync(0x11111111u, ssum, 4);
        ssum += __shfl_xor_sync(0x11111111u, ssum, 8);
        ssum += __shfl_xor_sync(0x11111111u, ssum, 16);
        WNf[row] = wraw / ssum;
    }
}

__global__ __launch_bounds__(NTHR, 1) void nerf_main(
    const float* __restrict__ map_xyz, const float* __restrict__ map_feat,
    const int* __restrict__ ind_voxel, const float* __restrict__ sample_xyz,
    const float* __restrict__ dist_cam,
    const float* __restrict__ W0, const float* __restrict__ b0,
    const float* __restrict__ W1, const float* __restrict__ b1,
    const float* __restrict__ W2, const float* __restrict__ b2,
    const float* __restrict__ Wa0, const float* __restrict__ ba0,
    const float* __restrict__ Wa1, const float* __restrict__ ba1,
    const float* __restrict__ Wr0, const float* __restrict__ br0,
    const float* __restrict__ Wr1, const float* __restrict__ br1,
    float* __restrict__ out) {
    extern __shared__ char smem[];
    const uint32_t sb = smem_u32(smem);
    const int t = threadIdx.x;
    const int w = t >> 5, lane = t & 31;
    const int rg = w >> 2;
    const int R = rg * 32;
    const int C = (w & 3) * 32;

    __half* B0h = (__half*)(smem + OFF_B0);
    __half* B1h = (__half*)(smem + OFF_B1);
    __half* B2h = (__half*)(smem + OFF_B2);
    __half* BHh = (__half*)(smem + OFF_BH);
    __half* WA1h = (__half*)(smem + OFF_WA1);
    __half* WR1h = (__half*)(smem + OFF_WR1);
    float* WNf = (float*)(smem + OFF_WN);

    // ---------- weights -> f16 swizzled tiles (once per persistent CTA) ----------
    for (int i = t; i < 8192; i += NTHR)
        ((uint32_t*)(smem + OFF_W0))[i] = 0u;
    __syncthreads();
    for (int e = t; e < 88 * 128; e += NTHR) {
        int k = e >> 7, n = e & 127;
        *(__half*)(smem + OFF_W0 + tadr(n, k)) = __float2half_rn(W0[e]);
    }
    for (int e = t; e < 16384; e += NTHR) {
        int k = e >> 7, n = e & 127;
        uint32_t so = tadr(n, k);
        *(__half*)(smem + OFF_W1 + so) = __float2half_rn(W1[e]);
        *(__half*)(smem + OFF_W2 + so) = __float2half_rn(W2[e]);
    }
    for (int e = t; e < 8192; e += NTHR) {
        int k = e >> 6, n = e & 63;
        *(__half*)(smem + OFF_WH + tadr(n, k)) = __float2half_rn(Wa0[e]);
        *(__half*)(smem + OFF_WH + tadr(n + 64, k)) = __float2half_rn(Wr0[e]);
    }
    if (t < 128) {
        B0h[t] = __float2half_rn(b0[t]);
        B1h[t] = __float2half_rn(b1[t]);
        B2h[t] = __float2half_rn(b2[t]);
    }
    if (t < 64) {
        BHh[t] = __float2half_rn(ba0[t]);
        BHh[64 + t] = __float2half_rn(br0[t]);
        WA1h[t] = __float2half_rn(Wa1[t]);
    }
    if (t < 192) WR1h[t] = __float2half_rn(Wr1[t]);

    // ---------- gather prefetch: first actual pair = (rg skewed) ----------
    const int p = t >> 2, q = t & 3;          // p's row group == rg
    float4 fv[4];
    float oax = 0.f;
    int idx1 = 0;
    {
        const int ap0 = rg & 3;
        const int gs0 = blockIdx.x * SUPER + ap0 * 32 + (p >> 3);
        const int idx = ind_voxel[gs0 * 8 + (p & 7)];
        const float4* f4 = (const float4*)map_feat + (size_t)idx * 16 + q * 4;
        fv[0] = f4[0]; fv[1] = f4[1]; fv[2] = f4[2]; fv[3] = f4[3];
        if (q) oax = sample_xyz[gs0 * 3 + q - 1] - map_xyz[idx * 3 + q - 1];
        const int gs1 = gs0 + 16;
        idx1 = ind_voxel[gs1 * 8 + (p & 7)];
        l2hint((const float4*)map_feat + (size_t)idx1 * 16 + q * 4);
        if (q) l2hint(map_xyz + idx1 * 3);
    }
    __syncthreads();   // weights ready

    float acc[16][4];
    __half2 hv[32];
    const int g = lane >> 2, tg = lane & 3;

    for (int bid = blockIdx.x; bid < NBLK; bid += gridDim.x) {
        for (int pp = 0; pp < PAIRS; pp++) {
            const int ap = (pp + rg) & 3;     // actual pair for this row group
            // ---------- store gathered pair rows -> A0 ----------
            {
                char* A0p = smem + OFF_A0;
                const int gs1 = bid * SUPER + ap * 32 + 16 + (p >> 3);
                const float4* f4b = (const float4*)map_feat + (size_t)idx1 * 16 + q * 4;
                float4 g0 = f4b[0], g1 = f4b[1], g2 = f4b[2], g3 = f4b[3];
                float oax1 = 0.f;
                if (q) oax1 = sample_xyz[gs1 * 3 + q - 1] - map_xyz[idx1 * 3 + q - 1];
                store_rows(A0p, p, fv[0], fv[1], fv[2], fv[3], q, oax, WNf);
                store_rows(A0p, 128 + p, g0, g1, g2, g3, q, oax1, WNf);
            }
            rg_bar(rg);

            // ---------- prefetch next pair (rg-skewed order) ----------
            {
                int nb = bid, anp;
                if (pp < 3) {
                    anp = (pp + 1 + rg) & 3;
                } else {
                    anp = rg & 3;
                    nb = bid + (int)gridDim.x;
                }
                if (nb < NBLK) {
                    const int gs0 = nb * SUPER + anp * 32 + (p >> 3);
                    const int idx = ind_voxel[gs0 * 8 + (p & 7)];
                    const float4* f4 = (const float4*)map_feat + (size_t)idx * 16 + q * 4;
                    fv[0] = f4[0]; fv[1] = f4[1]; fv[2] = f4[2]; fv[3] = f4[3];
                    if (q) oax = sample_xyz[gs0 * 3 + q - 1] - map_xyz[idx * 3 + q - 1];
                    const int gs1 = gs0 + 16;
                    idx1 = ind_voxel[gs1 * 8 + (p & 7)];
                    l2hint((const float4*)map_feat + (size_t)idx1 * 16 + q * 4);
                    if (q) l2hint(map_xyz + idx1 * 3);
                }
            }

            // ---------- layer 0 (K=96), in-place ----------
            layer_mma_pair<6>(sb + OFF_A0, sb + OFF_W0, R, C, lane, acc);
            {   // packed epilogue BEFORE the WAR barrier (regs only)
#pragma unroll
                for (int i = 0; i < 16; i++) {
                    int nt = i & 3;
                    __half2 bb = *(__half2*)((char*)B0h + (C + nt * 8 + tg * 2) * 2);
                    hv[i * 2 + 0] = biaslrelu2(acc[i][0], acc[i][1], bb);
                    hv[i * 2 + 1] = biaslrelu2(acc[i][2], acc[i][3], bb);
                }
            }
            rg_bar(rg);   // peer reads of A0 rows done
            {
                char* dst = smem + OFF_A0;
#pragma unroll
                for (int i = 0; i < 16; i++) {
                    int ti = i >> 3, mt = (i >> 2) & 1, nt = i & 3;
                    int r0 = ti * 128 + R + mt * 16 + g;
                    int col = C + nt * 8 + tg * 2;
                    *(__half2*)(dst + tadr(r0, col)) = hv[i * 2 + 0];
                    *(__half2*)(dst + tadr(r0 + 8, col)) = hv[i * 2 + 1];
                }
            }
            rg_bar(rg);

            // ---------- layer 1, in-place ----------
            layer_mma_pair<8>(sb + OFF_A0, sb + OFF_W1, R, C, lane, acc);
            {
#pragma unroll
                for (int i = 0; i < 16; i++) {
                    int nt = i & 3;
                    __half2 bb = *(__half2*)((char*)B1h + (C + nt * 8 + tg * 2) * 2);
                    hv[i * 2 + 0] = biaslrelu2(acc[i][0], acc[i][1], bb);
                    hv[i * 2 + 1] = biaslrelu2(acc[i][2], acc[i][3], bb);
                }
            }
            rg_bar(rg);
            {
                char* dst = smem + OFF_A0;
#pragma unroll
                for (int i = 0; i < 16; i++) {
                    int ti = i >> 3, mt = (i >> 2) & 1, nt = i & 3;
                    int r0 = ti * 128 + R + mt * 16 + g;
                    int col = C + nt * 8 + tg * 2;
                    *(__half2*)(dst + tadr(r0, col)) = hv[i * 2 + 0];
                    *(__half2*)(dst + tadr(r0 + 8, col)) = hv[i * 2 + 1];
                }
            }
            rg_bar(rg);

            // ---------- layer 2 -> weighted K-reduce (all-packed) -> FS ----------
            layer_mma_pair<8>(sb + OFF_A0, sb + OFF_W2, R, C, lane, acc);
            {
                char* FSp = smem + OFF_FS;
#pragma unroll
                for (int ti = 0; ti < 2; ti++) {
#pragma unroll
                    for (int mt = 0; mt < 2; mt++) {
                        const int Rm = R + mt * 16;
                        const float wn0 = WNf[ti * 128 + Rm + g];
                        const float wn1 = WNf[ti * 128 + Rm + 8 + g];
                        const int sA = ap * 32 + ti * 16 + (Rm >> 3);
#pragma unroll
                        for (int nt = 0; nt < 4; nt++) {
                            int col = C + nt * 8 + tg * 2;
                            float2 bb = __half22float2(*(__half2*)((char*)B2h + col * 2));
                            float* a = acc[ti * 8 + mt * 4 + nt];
                            uint32_t h01 = ph2(lrelu(a[0] + bb.x) * wn0,
                                               lrelu(a[1] + bb.y) * wn0);
                            uint32_t h23 = ph2(lrelu(a[2] + bb.x) * wn1,
                                               lrelu(a[3] + bb.y) * wn1);
                            h01 = hadd2u(h01, __shfl_xor_sync(0xFFFFFFFFu, h01, 4));
                            h23 = hadd2u(h23, __shfl_xor_sync(0xFFFFFFFFu, h23, 4));
                            h01 = hadd2u(h01, __shfl_xor_sync(0xFFFFFFFFu, h01, 8));
                            h23 = hadd2u(h23, __shfl_xor_sync(0xFFFFFFFFu, h23, 8));
                            h01 = hadd2u(h01, __shfl_xor_sync(0xFFFFFFFFu, h01, 16));
                            h23 = hadd2u(h23, __shfl_xor_sync(0xFFFFFFFFu, h23, 16));
                            if (g == 0) {
                                *(uint32_t*)(FSp + tadr(sA, col)) = h01;
                                *(uint32_t*)(FSp + tadr(sA + 1, col)) = h23;
                            }
                        }
                    }
                }
            }
            rg_bar(rg);   // A0/WN rows reusable for next pair in this row group
        }

        __syncthreads();  // all groups' FS writes visible

        // ---------- heads: FS x [Wa0|Wr0] -> A0 rows 0..127 (hidden) ----------
        {
            float (*acc8)[4] = (float (*)[4])acc;
            layer_mma<8>(sb + OFF_FS, sb + OFF_WH, R, C, lane, acc8);
            char* dst = smem + OFF_A0;
#pragma unroll
            for (int mt = 0; mt < 2; mt++) {
                int r0 = R + mt * 16 + g;
#pragma unroll
                for (int nt = 0; nt < 4; nt++) {
                    int col = C + nt * 8 + tg * 2;
                    __half2 bh = *(__half2*)((char*)BHh + col * 2);
                    float* a = acc8[mt * 4 + nt];
                    *(__half2*)(dst + tadr(r0, col)) = biaslrelu2(a[0], a[1], bh);
                    *(__half2*)(dst + tadr(r0 + 8, col)) = biaslrelu2(a[2], a[3], bh);
                }
            }
        }
        __syncthreads();

        // ---------- final projections + sigmoid -> SAMP (all 512 threads) ----------
        {
            char* Hp = smem + OFF_A0;
            float* SP = (float*)(smem + OFF_SAMP);
            if (t < 128) {                         // alpha for sample t
                float a = ba1[0];
#pragma unroll
                for (int m = 0; m < 32; m++) {
                    float2 v = __half22float2(*(__half2*)(Hp + tadr(t, 2 * m)));
                    float2 wv = __half22float2(((__half2*)WA1h)[m]);
                    a += v.x * wv.x + v.y * wv.y;
                }
                SP[t * 4 + 0] = 1.f / (1.f + __expf(-a));
            } else {                               // rgb: one (sample, channel) per thread
                int e = t - 128;                   // 0..383
                int s = e >> 2 | 0;                // (re-derived below to cover 128*3)
                // map e -> (s, ch): 384 threads, s = e / 3, ch = e % 3
                s = e / 3;
                int ch = e - s * 3;
                float a = br1[ch];
#pragma unroll
                for (int m = 0; m < 32; m++) {
                    float2 v = __half22float2(*(__half2*)(Hp + tadr(s, 64 + 2 * m)));
                    int j = 2 * m;
                    a += v.x * __half2float(WR1h[j * 3 + ch]) +
                         v.y * __half2float(WR1h[j * 3 + 3 + ch]);
                }
                SP[s * 4 + 1 + ch] = 1.f / (1.f + __expf(-a));
            }
        }
        __syncthreads();

        // ---------- fused volume rendering: 2 rays per group ----------
        if (w < 2) {
            const int ray = bid * 2 + w;
            const float4* sp = (const float4*)(smem + OFF_SAMP) + w * 64;
            const float* dp = dist_cam + ray * 64;
            float cr = 0, cg = 0, cb = 0, cd = 0, ca = 0, carry = 0;
#pragma unroll
            for (int hh = 0; hh < 2; hh++) {
                float4 v = sp[hh * 32 + lane];
                float l = __logf(1.f - v.x + 1e-10f);
                float s = l;
#pragma unroll
                for (int o = 1; o < 32; o <<= 1) {
                    float n = __shfl_up_sync(0xFFFFFFFFu, s, o);
                    if (lane >= o) s += n;
                }
                float T = __expf(carry + s - l);    // exclusive prefix product
                float b = v.x * T;
                float d = 1.0f + 80.0f * dp[hh * 32 + lane] / 64.0f;
                cr += v.y * b; cg += v.z * b; cb += v.w * b; cd += d * b; ca += b;
                carry += __shfl_sync(0xFFFFFFFFu, s, 31);
            }
#pragma unroll
            for (int o = 16; o; o >>= 1) {
                cr += __shfl_down_sync(0xFFFFFFFFu, cr, o);
                cg += __shfl_down_sync(0xFFFFFFFFu, cg, o);
                cb += __shfl_down_sync(0xFFFFFFFFu, cb, o);
                cd += __shfl_down_sync(0xFFFFFFFFu, cd, o);
                ca += __shfl_down_sync(0xFFFFFFFFu, ca, o);
            }
            if (lane == 0) {
                out[ray * 5 + 0] = cr; out[ray * 5 + 1] = cg; out[ray * 5 + 2] = cb;
                out[ray * 5 + 3] = cd; out[ray * 5 + 4] = ca;
            }
        }
        __syncthreads();   // SAMP/A0 reads done before next group's gather stores
    }
}

extern "C" void kernel_launch(void* const* d_in, const int* in_sizes, int n_in,
                              void* d_out, int out_size) {
    cudaFuncSetAttribute(nerf_main, cudaFuncAttributeMaxDynamicSharedMemorySize,
                         SMEM_TOTAL);
    nerf_main<<<NCTA, NTHR, SMEM_TOTAL>>>(
        (const float*)d_in[0], (const float*)d_in[1], (const int*)d_in[2],
        (const float*)d_in[3], (const float*)d_in[4],
        (const float*)d_in[5], (const float*)d_in[6], (const float*)d_in[7],
        (const float*)d_in[8], (const float*)d_in[9], (const float*)d_in[10],
        (const float*)d_in[11], (const float*)d_in[12], (const float*)d_in[13],
        (const float*)d_in[14], (const float*)d_in[15], (const float*)d_in[16],
        (const float*)d_in[17], (const float*)d_in[18], (float*)d_out);
}